// round 4
// baseline (speedup 1.0000x reference)
#include <cuda_runtime.h>
#include <cuda_bf16.h>
#include <cstdint>

// ---------------------------------------------------------------------------
// CTRGC round 4: warp-level HMMA (mma.sync.m16n8k16.bf16, 3-term split) for the
// channel GEMM + proven fp32x2 graph-mix epilogue.
//
// out[n,o,t,w] = relu( sum_k sum_v (sum_c Weff[k][o,c] x[n,c,t,v]) M_k[v,w] + Ceff[o] )
// N=128, Cin=Cout=64, T=256, V=18, K=3.
//
// Tile = (n, 8 t's): GEMM  Y[pos=(t,v), 144 rows][(k,o), 192 cols] = X'[144x64] * W^T
// on tensor cores; then O[t,o,w] = Ceff + sum_{k,v} Y M_k in fp32x2.
// Fragments are packed analytically (no ldmatrix).
// ---------------------------------------------------------------------------

#define TFULL 256
#define CIN 64
#define VD 18
#define VP 20
#define TT 8
#define MROWS 144          // 8*18
#define NSTRIPS 9          // 144/16
#define NCOLS 192
#define NBLK 24            // 192/8
#define NTILES 4096        // 128 n * 32 tiles
#define THREADS 512
#define GRID 148

// ---- smem byte offsets ----
#define OFF_BH 0                               // B frags hi: 24*4*32*8 = 24576
#define OFF_BL (OFF_BH + NBLK * 4 * 32 * 8)    // 24576
#define OFF_AH (OFF_BL + NBLK * 4 * 32 * 8)    // 49152 ; A frags hi: 9*4*32*16 = 18432
#define OFF_AL (OFF_AH + NSTRIPS * 4 * 32 * 16)
#define OFF_Y  (OFF_AL + NSTRIPS * 4 * 32 * 16)        // sY: 144 x 200 floats
#define YSTRIDE 200
#define OFF_M  (OFF_Y + MROWS * YSTRIDE * 4)
#define OFF_C  (OFF_M + 3 * VD * VP * 4)
#define SMEM_BYTES (OFF_C + 256)

// prepped parameters
__device__ unsigned long long d_BfragHi[NBLK * 4 * 32];  // [(nb*4+ks)*32+lane] -> {b0,b1}
__device__ unsigned long long d_BfragLo[NBLK * 4 * 32];
__device__ float d_Cf[64];
__device__ float d_M[3 * VD * VP];

__device__ __forceinline__ uint32_t pack2bf(float x, float y) {
    __nv_bfloat162 t = __floats2bfloat162_rn(x, y);   // x -> low half
    return *reinterpret_cast<uint32_t*>(&t);
}

__global__ void prep_kernel(const float* __restrict__ A, const float* __restrict__ PA,
                            const float* __restrict__ Wta, const float* __restrict__ bta,
                            const float* __restrict__ g_ta, const float* __restrict__ b_ta,
                            const float* __restrict__ m_ta, const float* __restrict__ v_ta,
                            const float* __restrict__ g_bn, const float* __restrict__ b_bn,
                            const float* __restrict__ m_bn, const float* __restrict__ v_bn)
{
    int tid = threadIdx.x;
    // B fragments: b0 = {W[n][c0], W[n][c0+1]}, b1 = {W[n][c0+8], W[n][c0+9]}
    for (int idx = tid; idx < NBLK * 4 * 32; idx += blockDim.x) {
        int nb = idx >> 7;
        int ks = (idx >> 5) & 3;
        int lane = idx & 31;
        int g = lane >> 2, tig = lane & 3;
        int n = nb * 8 + g;
        int k = n >> 6, o = n & 63;
        float s2 = g_bn[o] * rsqrtf(v_bn[o] + 1e-5f);
        float s1 = g_ta[k * 64 + o] * rsqrtf(v_ta[k * 64 + o] + 1e-5f);
        float s = s2 * s1;
        int c0 = ks * 16 + 2 * tig;
        float wv[4];
        wv[0] = s * Wta[(k * 64 + o) * 64 + c0];
        wv[1] = s * Wta[(k * 64 + o) * 64 + c0 + 1];
        wv[2] = s * Wta[(k * 64 + o) * 64 + c0 + 8];
        wv[3] = s * Wta[(k * 64 + o) * 64 + c0 + 9];
        float hf[4], lf[4];
#pragma unroll
        for (int i = 0; i < 4; i++) {
            __nv_bfloat16 h = __float2bfloat16(wv[i]);
            hf[i] = __bfloat162float(h);
            lf[i] = wv[i] - hf[i];
        }
        uint32_t h0 = pack2bf(hf[0], hf[1]);
        uint32_t h1 = pack2bf(hf[2], hf[3]);
        uint32_t l0 = pack2bf(lf[0], lf[1]);
        uint32_t l1 = pack2bf(lf[2], lf[3]);
        d_BfragHi[idx] = ((unsigned long long)h1 << 32) | h0;
        d_BfragLo[idx] = ((unsigned long long)l1 << 32) | l0;
    }
    if (tid < 64) {
        int o = tid;
        float s2 = g_bn[o] * rsqrtf(v_bn[o] + 1e-5f);
        float acc = 0.0f;
        for (int k = 0; k < 3; k++) {
            float s1 = g_ta[k * 64 + o] * rsqrtf(v_ta[k * 64 + o] + 1e-5f);
            acc += s1 * (bta[k * 64 + o] - m_ta[k * 64 + o]) + b_ta[k * 64 + o];
        }
        d_Cf[o] = s2 * acc + b_bn[o] - m_bn[o] * s2;
    }
    for (int idx = tid; idx < 3 * VD * VP; idx += blockDim.x) {
        int k = idx / (VD * VP);
        int r = idx - k * (VD * VP);
        int v = r / VP;
        int w = r - v * VP;
        d_M[idx] = (w < VD) ? (A[(k * VD + v) * VD + w] + PA[(k * VD + v) * VD + w]) : 0.0f;
    }
}

// ---- HMMA m16n8k16 bf16, f32 accum ----
__device__ __forceinline__ void mma_bf16(float* d, uint32_t a0, uint32_t a1,
                                         uint32_t a2, uint32_t a3,
                                         uint32_t b0, uint32_t b1) {
    asm("mma.sync.aligned.m16n8k16.row.col.f32.bf16.bf16.f32 "
        "{%0,%1,%2,%3},{%4,%5,%6,%7},{%8,%9},{%0,%1,%2,%3};"
        : "+f"(d[0]), "+f"(d[1]), "+f"(d[2]), "+f"(d[3])
        : "r"(a0), "r"(a1), "r"(a2), "r"(a3), "r"(b0), "r"(b1));
}

// ---- packed f32x2 helpers ----
__device__ __forceinline__ unsigned long long pk2(float a, float b) {
    unsigned long long r;
    asm("mov.b64 %0, {%1,%2};" : "=l"(r) : "f"(a), "f"(b));
    return r;
}
__device__ __forceinline__ void upk2(unsigned long long p, float& a, float& b) {
    asm("mov.b64 {%0,%1}, %2;" : "=f"(a), "=f"(b) : "l"(p));
}
__device__ __forceinline__ unsigned long long fma2(unsigned long long a,
                                                   unsigned long long b,
                                                   unsigned long long c) {
    unsigned long long d;
    asm("fma.rn.f32x2 %0, %1, %2, %3;" : "=l"(d) : "l"(a), "l"(b), "l"(c));
    return d;
}

extern __shared__ char smem[];

__global__ __launch_bounds__(THREADS, 1)
void ctrgc_hmma(const float* __restrict__ x, float* __restrict__ out)
{
    const int tid = threadIdx.x;
    const int w = tid >> 5;
    const int lane = tid & 31;
    const int g = lane >> 2;
    const int tig = lane & 3;

    float* sY = reinterpret_cast<float*>(smem + OFF_Y);
    float* sM = reinterpret_cast<float*>(smem + OFF_M);
    float* sC = reinterpret_cast<float*>(smem + OFF_C);
    __nv_bfloat16* sAh = reinterpret_cast<__nv_bfloat16*>(smem + OFF_AH);
    __nv_bfloat16* sAl = reinterpret_cast<__nv_bfloat16*>(smem + OFF_AL);

    // one-time: B frags, M, C into smem
    {
        unsigned long long* bh = reinterpret_cast<unsigned long long*>(smem + OFF_BH);
        unsigned long long* bl = reinterpret_cast<unsigned long long*>(smem + OFF_BL);
        for (int i = tid; i < NBLK * 4 * 32; i += THREADS) {
            bh[i] = d_BfragHi[i];
            bl[i] = d_BfragLo[i];
        }
        for (int i = tid; i < 3 * VD * VP; i += THREADS) sM[i] = d_M[i];
        if (tid < 64) sC[tid] = d_Cf[tid];
    }
    __syncthreads();

    const int t_loc = tid >> 6;   // 0..7
    const int o     = tid & 63;

    for (int tile = blockIdx.x; tile < NTILES; tile += GRID) {
        const int n  = tile >> 5;
        const int t0 = (tile & 31) * TT;

        // ---- convert x tile -> fragment-packed A hi/lo ----
        // X'[pos][c] = x[n][c][t0*18 + pos], pos = t_loc*18 + v (144 pos)
        const float* xn = x + (size_t)n * (CIN * TFULL * VD) + (size_t)t0 * VD;
        for (int i = tid; i < CIN * MROWS; i += THREADS) {
            int c = i / MROWS;
            int pos = i - c * MROWS;
            float v = xn[c * (TFULL * VD) + pos];
            __nv_bfloat16 hb = __float2bfloat16(v);
            float lof = v - __bfloat162float(hb);
            __nv_bfloat16 lb = __float2bfloat16(lof);
            int strip = pos >> 4, r = pos & 15;
            int ks = c >> 4, cc = c & 15;
            int fl = (r & 7) * 4 + ((cc >> 1) & 3);
            int reg = (r >> 3) + 2 * (cc >> 3);
            int idx = (((strip * 4 + ks) * 32 + fl) << 3) + reg * 2 + (cc & 1);
            sAh[idx] = hb;
            sAl[idx] = lb;
        }
        __syncthreads();

        // ---- stage A: HMMA jobs (strip, n-half), 18 jobs over 16 warps ----
        for (int job = w; job < NSTRIPS * 2; job += 16) {
            int strip = job >> 1;
            int nh = job & 1;
            float D[12][4];
#pragma unroll
            for (int b = 0; b < 12; b++)
#pragma unroll
                for (int q = 0; q < 4; q++) D[b][q] = 0.0f;

#pragma unroll
            for (int ks = 0; ks < 4; ks++) {
                const uint4 ah = *reinterpret_cast<const uint4*>(
                    smem + OFF_AH + (((strip * 4 + ks) * 32 + lane) << 4));
                const uint4 al = *reinterpret_cast<const uint4*>(
                    smem + OFF_AL + (((strip * 4 + ks) * 32 + lane) << 4));
#pragma unroll
                for (int b = 0; b < 12; b++) {
                    int nb = nh * 12 + b;
                    unsigned long long bh = *reinterpret_cast<const unsigned long long*>(
                        smem + OFF_BH + (((nb * 4 + ks) * 32 + lane) << 3));
                    unsigned long long bl = *reinterpret_cast<const unsigned long long*>(
                        smem + OFF_BL + (((nb * 4 + ks) * 32 + lane) << 3));
                    uint32_t bh0 = (uint32_t)bh, bh1 = (uint32_t)(bh >> 32);
                    uint32_t bl0 = (uint32_t)bl, bl1 = (uint32_t)(bl >> 32);
                    mma_bf16(D[b], ah.x, ah.y, ah.z, ah.w, bh0, bh1);  // hi*hi
                    mma_bf16(D[b], ah.x, ah.y, ah.z, ah.w, bl0, bl1);  // hi*lo
                    mma_bf16(D[b], al.x, al.y, al.z, al.w, bh0, bh1);  // lo*hi
                }
            }
            // D -> sY
            int row0 = strip * 16 + g;
#pragma unroll
            for (int b = 0; b < 12; b++) {
                int n0 = (nh * 12 + b) * 8;
                *reinterpret_cast<float2*>(sY + row0 * YSTRIDE + n0 + 2 * tig) =
                    make_float2(D[b][0], D[b][1]);
                *reinterpret_cast<float2*>(sY + (row0 + 8) * YSTRIDE + n0 + 2 * tig) =
                    make_float2(D[b][2], D[b][3]);
            }
        }
        __syncthreads();

        // ---- stage B: O[w] = Ceff[o] + sum_k sum_v Y[(t,v)][(k,o)] * M_k[v][w] ----
        unsigned long long O[9];
        {
            float cf = sC[o];
            unsigned long long cp = pk2(cf, cf);
#pragma unroll
            for (int q = 0; q < 9; q++) O[q] = cp;
        }

#pragma unroll
        for (int k = 0; k < 3; k++) {
            const float* yb = sY + (t_loc * VD) * YSTRIDE + k * 64 + o;
#pragma unroll
            for (int pv = 0; pv < 9; pv++) {
                float y0 = yb[(2 * pv) * YSTRIDE];
                float y1 = yb[(2 * pv + 1) * YSTRIDE];
                unsigned long long Y0 = pk2(y0, y0);
                unsigned long long Y1 = pk2(y1, y1);
                const float* m0 = sM + (k * VD + 2 * pv) * VP;
                const float* m1 = m0 + VP;
                {
                    ulonglong2 r0 = *reinterpret_cast<const ulonglong2*>(m0);
                    ulonglong2 r1 = *reinterpret_cast<const ulonglong2*>(m0 + 4);
                    ulonglong2 r2 = *reinterpret_cast<const ulonglong2*>(m0 + 8);
                    ulonglong2 r3 = *reinterpret_cast<const ulonglong2*>(m0 + 12);
                    unsigned long long r4 = *reinterpret_cast<const unsigned long long*>(m0 + 16);
                    O[0] = fma2(Y0, r0.x, O[0]); O[1] = fma2(Y0, r0.y, O[1]);
                    O[2] = fma2(Y0, r1.x, O[2]); O[3] = fma2(Y0, r1.y, O[3]);
                    O[4] = fma2(Y0, r2.x, O[4]); O[5] = fma2(Y0, r2.y, O[5]);
                    O[6] = fma2(Y0, r3.x, O[6]); O[7] = fma2(Y0, r3.y, O[7]);
                    O[8] = fma2(Y0, r4,   O[8]);
                }
                {
                    ulonglong2 r0 = *reinterpret_cast<const ulonglong2*>(m1);
                    ulonglong2 r1 = *reinterpret_cast<const ulonglong2*>(m1 + 4);
                    ulonglong2 r2 = *reinterpret_cast<const ulonglong2*>(m1 + 8);
                    ulonglong2 r3 = *reinterpret_cast<const ulonglong2*>(m1 + 12);
                    unsigned long long r4 = *reinterpret_cast<const unsigned long long*>(m1 + 16);
                    O[0] = fma2(Y1, r0.x, O[0]); O[1] = fma2(Y1, r0.y, O[1]);
                    O[2] = fma2(Y1, r1.x, O[2]); O[3] = fma2(Y1, r1.y, O[3]);
                    O[4] = fma2(Y1, r2.x, O[4]); O[5] = fma2(Y1, r2.y, O[5]);
                    O[6] = fma2(Y1, r3.x, O[6]); O[7] = fma2(Y1, r3.y, O[7]);
                    O[8] = fma2(Y1, r4,   O[8]);
                }
            }
        }

        // ---- relu + store ----
        {
            float* op = out + ((size_t)(n * 64 + o) * TFULL + (t0 + t_loc)) * VD;
#pragma unroll
            for (int q = 0; q < 9; q++) {
                float a, b;
                upk2(O[q], a, b);
                *reinterpret_cast<float2*>(op + 2 * q) =
                    make_float2(fmaxf(a, 0.0f), fmaxf(b, 0.0f));
            }
        }
        __syncthreads();   // sY/sA reuse next tile
    }
}

extern "C" void kernel_launch(void* const* d_in, const int* in_sizes, int n_in,
                              void* d_out, int out_size)
{
    (void)in_sizes; (void)n_in; (void)out_size;
    const float* x    = (const float*)d_in[0];
    const float* A    = (const float*)d_in[1];
    const float* PA   = (const float*)d_in[2];
    const float* Wta  = (const float*)d_in[3];
    const float* bta  = (const float*)d_in[4];
    const float* g_ta = (const float*)d_in[5];
    const float* b_ta = (const float*)d_in[6];
    const float* m_ta = (const float*)d_in[7];
    const float* v_ta = (const float*)d_in[8];
    // d_in[9..12] dead attention branch
    const float* g_bn = (const float*)d_in[13];
    const float* b_bn = (const float*)d_in[14];
    const float* m_bn = (const float*)d_in[15];
    const float* v_bn = (const float*)d_in[16];
    float* out = (float*)d_out;

    cudaFuncSetAttribute(ctrgc_hmma, cudaFuncAttributeMaxDynamicSharedMemorySize, SMEM_BYTES);

    prep_kernel<<<1, 256>>>(A, PA, Wta, bta, g_ta, b_ta, m_ta, v_ta,
                            g_bn, b_bn, m_bn, v_bn);
    ctrgc_hmma<<<GRID, THREADS, SMEM_BYTES>>>(x, out);
}

// round 5
// speedup vs baseline: 1.5680x; 1.5680x over previous
#include <cuda_runtime.h>
#include <cuda_bf16.h>
#include <cstdint>

// ---------------------------------------------------------------------------
// CTRGC round 5: round-4 HMMA dataflow with a fixed schedule:
//  - TT=7 -> 128 padded rows = 8 strips x 2 n-halves = exactly 16 warp jobs
//  - 2 barriers/tile; next-tile conversion + LDG prefetch overlap stage B
//  - 4736 tiles = 148 CTAs x 32 tiles exactly (no wave tail)
// ---------------------------------------------------------------------------

#define TFULL 256
#define CIN 64
#define VD 18
#define VP 20
#define TT 7
#define MROWS 126          // 7*18 real rows
#define PADROWS 128
#define NSTRIPS 8
#define NCOLS 192
#define NBLK 24
#define TILES_PER_N 37     // last tile has 4 valid t
#define TILES_PER_CTA 32
#define NTILES 4736        // 128 * 37 = 148 * 32
#define THREADS 512
#define GRID 148
#define YSTRIDE 196

// ---- smem byte offsets ----
#define OFF_BH 0                                   // 24 blk * 4 ks * 32 lanes * 8B = 24576
#define OFF_BL (OFF_BH + NBLK * 4 * 32 * 8)        // 24576
#define OFF_AH (OFF_BL + NBLK * 4 * 32 * 8)        // 49152 ; 8 strips*4*32*16 = 16384
#define OFF_AL (OFF_AH + NSTRIPS * 4 * 32 * 16)    // 65536
#define OFF_Y  (OFF_AL + NSTRIPS * 4 * 32 * 16)    // 81920 ; 128 x 196 f32 = 100352
#define OFF_M  (OFF_Y + PADROWS * YSTRIDE * 4)     // 182272
#define OFF_C  (OFF_M + 3 * VD * VP * 4)           // 186592
#define SMEM_BYTES (OFF_C + 256)

// prepped parameters
__device__ unsigned long long d_BfragHi[NBLK * 4 * 32];
__device__ unsigned long long d_BfragLo[NBLK * 4 * 32];
__device__ float d_Cf[64];
__device__ float d_M[3 * VD * VP];

__device__ __forceinline__ uint32_t pack2bf(float x, float y) {
    __nv_bfloat162 t = __floats2bfloat162_rn(x, y);
    return *reinterpret_cast<uint32_t*>(&t);
}

__global__ void prep_kernel(const float* __restrict__ A, const float* __restrict__ PA,
                            const float* __restrict__ Wta, const float* __restrict__ bta,
                            const float* __restrict__ g_ta, const float* __restrict__ b_ta,
                            const float* __restrict__ m_ta, const float* __restrict__ v_ta,
                            const float* __restrict__ g_bn, const float* __restrict__ b_bn,
                            const float* __restrict__ m_bn, const float* __restrict__ v_bn)
{
    int tid = threadIdx.x;
    for (int idx = tid; idx < NBLK * 4 * 32; idx += blockDim.x) {
        int nb = idx >> 7;
        int ks = (idx >> 5) & 3;
        int lane = idx & 31;
        int g = lane >> 2, tig = lane & 3;
        int n = nb * 8 + g;
        int k = n >> 6, o = n & 63;
        float s2 = g_bn[o] * rsqrtf(v_bn[o] + 1e-5f);
        float s1 = g_ta[k * 64 + o] * rsqrtf(v_ta[k * 64 + o] + 1e-5f);
        float s = s2 * s1;
        int c0 = ks * 16 + 2 * tig;
        float wv[4];
        wv[0] = s * Wta[(k * 64 + o) * 64 + c0];
        wv[1] = s * Wta[(k * 64 + o) * 64 + c0 + 1];
        wv[2] = s * Wta[(k * 64 + o) * 64 + c0 + 8];
        wv[3] = s * Wta[(k * 64 + o) * 64 + c0 + 9];
        float hf[4], lf[4];
#pragma unroll
        for (int i = 0; i < 4; i++) {
            __nv_bfloat16 h = __float2bfloat16(wv[i]);
            hf[i] = __bfloat162float(h);
            lf[i] = wv[i] - hf[i];
        }
        d_BfragHi[idx] = ((unsigned long long)pack2bf(hf[2], hf[3]) << 32) | pack2bf(hf[0], hf[1]);
        d_BfragLo[idx] = ((unsigned long long)pack2bf(lf[2], lf[3]) << 32) | pack2bf(lf[0], lf[1]);
    }
    if (tid < 64) {
        int o = tid;
        float s2 = g_bn[o] * rsqrtf(v_bn[o] + 1e-5f);
        float acc = 0.0f;
        for (int k = 0; k < 3; k++) {
            float s1 = g_ta[k * 64 + o] * rsqrtf(v_ta[k * 64 + o] + 1e-5f);
            acc += s1 * (bta[k * 64 + o] - m_ta[k * 64 + o]) + b_ta[k * 64 + o];
        }
        d_Cf[o] = s2 * acc + b_bn[o] - m_bn[o] * s2;
    }
    for (int idx = tid; idx < 3 * VD * VP; idx += blockDim.x) {
        int k = idx / (VD * VP);
        int r = idx - k * (VD * VP);
        int v = r / VP;
        int w = r - v * VP;
        d_M[idx] = (w < VD) ? (A[(k * VD + v) * VD + w] + PA[(k * VD + v) * VD + w]) : 0.0f;
    }
}

// ---- HMMA m16n8k16 bf16, f32 accum ----
__device__ __forceinline__ void mma_bf16(float* d, uint32_t a0, uint32_t a1,
                                         uint32_t a2, uint32_t a3,
                                         uint32_t b0, uint32_t b1) {
    asm("mma.sync.aligned.m16n8k16.row.col.f32.bf16.bf16.f32 "
        "{%0,%1,%2,%3},{%4,%5,%6,%7},{%8,%9},{%0,%1,%2,%3};"
        : "+f"(d[0]), "+f"(d[1]), "+f"(d[2]), "+f"(d[3])
        : "r"(a0), "r"(a1), "r"(a2), "r"(a3), "r"(b0), "r"(b1));
}

// ---- packed f32x2 helpers ----
__device__ __forceinline__ unsigned long long pk2(float a, float b) {
    unsigned long long r;
    asm("mov.b64 %0, {%1,%2};" : "=l"(r) : "f"(a), "f"(b));
    return r;
}
__device__ __forceinline__ void upk2(unsigned long long p, float& a, float& b) {
    asm("mov.b64 {%0,%1}, %2;" : "=f"(a), "=f"(b) : "l"(p));
}
__device__ __forceinline__ unsigned long long fma2(unsigned long long a,
                                                   unsigned long long b,
                                                   unsigned long long c) {
    unsigned long long d;
    asm("fma.rn.f32x2 %0, %1, %2, %3;" : "=l"(d) : "l"(a), "l"(b), "l"(c));
    return d;
}

extern __shared__ char smem[];

// pack one x value into A-fragment layout (hi+lo), pos<MROWS assumed
__device__ __forceinline__ void pack_A(char* base_hi, char* base_lo, int c, int pos, float v) {
    __nv_bfloat16 hb = __float2bfloat16(v);
    __nv_bfloat16 lb = __float2bfloat16(v - __bfloat162float(hb));
    int strip = pos >> 4, r = pos & 15;
    int ks = c >> 4, cc = c & 15;
    int fl = (r & 7) * 4 + ((cc >> 1) & 3);
    int reg = (r >> 3) + 2 * (cc >> 3);
    int byteoff = (((strip * 4 + ks) * 32 + fl) << 4) + reg * 4 + (cc & 1) * 2;
    *reinterpret_cast<__nv_bfloat16*>(base_hi + byteoff) = hb;
    *reinterpret_cast<__nv_bfloat16*>(base_lo + byteoff) = lb;
}

__global__ __launch_bounds__(THREADS, 1)
void ctrgc_hmma5(const float* __restrict__ x, float* __restrict__ out)
{
    const int tid = threadIdx.x;
    const int w = tid >> 5;
    const int lane = tid & 31;
    const int g = lane >> 2;
    const int tig = lane & 3;

    float* sY = reinterpret_cast<float*>(smem + OFF_Y);
    float* sM = reinterpret_cast<float*>(smem + OFF_M);
    float* sC = reinterpret_cast<float*>(smem + OFF_C);

    // one-time: B frags, M, C into smem; zero A-frag regions (covers pad rows)
    {
        unsigned long long* bh = reinterpret_cast<unsigned long long*>(smem + OFF_BH);
        unsigned long long* bl = reinterpret_cast<unsigned long long*>(smem + OFF_BL);
        for (int i = tid; i < NBLK * 4 * 32; i += THREADS) {
            bh[i] = d_BfragHi[i];
            bl[i] = d_BfragLo[i];
        }
        uint32_t* az = reinterpret_cast<uint32_t*>(smem + OFF_AH);
        for (int i = tid; i < (OFF_Y - OFF_AH) / 4; i += THREADS) az[i] = 0u;
        for (int i = tid; i < 3 * VD * VP; i += THREADS) sM[i] = d_M[i];
        if (tid < 64) sC[tid] = d_Cf[tid];
    }

    const int t_loc = tid >> 6;   // 0..7 (<=6 valid normally)
    const int o     = tid & 63;

    const int tile0 = blockIdx.x * TILES_PER_CTA;

    // ---- prologue: convert tile0 ----
    {
        int n = tile0 / TILES_PER_N;
        int j = tile0 - n * TILES_PER_N;
        int t0 = j * TT;
        int nvalid = ((t0 + TT <= TFULL) ? TT : (TFULL - t0)) * VD;
        const float* xn = x + (size_t)n * (CIN * TFULL * VD) + (size_t)t0 * VD;
#pragma unroll
        for (int u = 0; u < 16; u++) {
            int i = tid + u * THREADS;      // 0..8191
            int c = i >> 7, pos = i & 127;
            if (pos < MROWS) {
                float v = (pos < nvalid) ? xn[c * (TFULL * VD) + pos] : 0.0f;
                pack_A(smem + OFF_AH, smem + OFF_AL, c, pos, v);
            }
        }
    }
    __syncthreads();

    for (int rel = 0; rel < TILES_PER_CTA; rel++) {
        const int tile = tile0 + rel;
        const int n  = tile / TILES_PER_N;
        const int j  = tile - n * TILES_PER_N;
        const int t0 = j * TT;
        const int valid_t = (t0 + TT <= TFULL) ? TT : (TFULL - t0);

        // ================= phase 1: HMMA (16 balanced jobs) + D -> sY =======
        {
            const int strip = w >> 1;
            const int nh = w & 1;
            float D[12][4];
#pragma unroll
            for (int b = 0; b < 12; b++)
#pragma unroll
                for (int q = 0; q < 4; q++) D[b][q] = 0.0f;

#pragma unroll
            for (int ks = 0; ks < 4; ks++) {
                const uint4 ah = *reinterpret_cast<const uint4*>(
                    smem + OFF_AH + (((strip * 4 + ks) * 32 + lane) << 4));
                const uint4 al = *reinterpret_cast<const uint4*>(
                    smem + OFF_AL + (((strip * 4 + ks) * 32 + lane) << 4));
#pragma unroll
                for (int b = 0; b < 12; b++) {
                    int nb = nh * 12 + b;
                    unsigned long long bhv = *reinterpret_cast<const unsigned long long*>(
                        smem + OFF_BH + (((nb * 4 + ks) * 32 + lane) << 3));
                    unsigned long long blv = *reinterpret_cast<const unsigned long long*>(
                        smem + OFF_BL + (((nb * 4 + ks) * 32 + lane) << 3));
                    uint32_t bh0 = (uint32_t)bhv, bh1 = (uint32_t)(bhv >> 32);
                    uint32_t bl0 = (uint32_t)blv, bl1 = (uint32_t)(blv >> 32);
                    mma_bf16(D[b], ah.x, ah.y, ah.z, ah.w, bh0, bh1);
                    mma_bf16(D[b], ah.x, ah.y, ah.z, ah.w, bl0, bl1);
                    mma_bf16(D[b], al.x, al.y, al.z, al.w, bh0, bh1);
                }
            }
            int row0 = strip * 16 + g;
#pragma unroll
            for (int b = 0; b < 12; b++) {
                int n0 = (nh * 12 + b) * 8;
                *reinterpret_cast<float2*>(sY + row0 * YSTRIDE + n0 + 2 * tig) =
                    make_float2(D[b][0], D[b][1]);
                *reinterpret_cast<float2*>(sY + (row0 + 8) * YSTRIDE + n0 + 2 * tig) =
                    make_float2(D[b][2], D[b][3]);
            }
        }
        __syncthreads();

        // ============== phase 2: prefetch(next) | stage B + store | pack(next)
        const bool hasNext = (rel + 1 < TILES_PER_CTA);
        float pf[16];
        int nxt_nvalid = 0;
        const float* xnn = nullptr;
        if (hasNext) {
            int tn = tile + 1;
            int nn = tn / TILES_PER_N;
            int jn = tn - nn * TILES_PER_N;
            int tn0 = jn * TT;
            nxt_nvalid = ((tn0 + TT <= TFULL) ? TT : (TFULL - tn0)) * VD;
            xnn = x + (size_t)nn * (CIN * TFULL * VD) + (size_t)tn0 * VD;
#pragma unroll
            for (int u = 0; u < 16; u++) {
                int i = tid + u * THREADS;
                int c = i >> 7, pos = i & 127;
                pf[u] = (pos < nxt_nvalid) ? __ldg(xnn + c * (TFULL * VD) + pos) : 0.0f;
            }
        }

        // ---- stage B (fp32x2) ----
        if (t_loc < valid_t) {
            unsigned long long O[9];
            {
                float cf = sC[o];
                unsigned long long cp = pk2(cf, cf);
#pragma unroll
                for (int q = 0; q < 9; q++) O[q] = cp;
            }
#pragma unroll
            for (int k = 0; k < 3; k++) {
                const float* yb = sY + (t_loc * VD) * YSTRIDE + k * 64 + o;
#pragma unroll
                for (int pv = 0; pv < 9; pv++) {
                    float y0 = yb[(2 * pv) * YSTRIDE];
                    float y1 = yb[(2 * pv + 1) * YSTRIDE];
                    unsigned long long Y0 = pk2(y0, y0);
                    unsigned long long Y1 = pk2(y1, y1);
                    const float* m0 = sM + (k * VD + 2 * pv) * VP;
                    const float* m1 = m0 + VP;
                    {
                        ulonglong2 r0 = *reinterpret_cast<const ulonglong2*>(m0);
                        ulonglong2 r1 = *reinterpret_cast<const ulonglong2*>(m0 + 4);
                        ulonglong2 r2 = *reinterpret_cast<const ulonglong2*>(m0 + 8);
                        ulonglong2 r3 = *reinterpret_cast<const ulonglong2*>(m0 + 12);
                        unsigned long long r4 = *reinterpret_cast<const unsigned long long*>(m0 + 16);
                        O[0] = fma2(Y0, r0.x, O[0]); O[1] = fma2(Y0, r0.y, O[1]);
                        O[2] = fma2(Y0, r1.x, O[2]); O[3] = fma2(Y0, r1.y, O[3]);
                        O[4] = fma2(Y0, r2.x, O[4]); O[5] = fma2(Y0, r2.y, O[5]);
                        O[6] = fma2(Y0, r3.x, O[6]); O[7] = fma2(Y0, r3.y, O[7]);
                        O[8] = fma2(Y0, r4,   O[8]);
                    }
                    {
                        ulonglong2 r0 = *reinterpret_cast<const ulonglong2*>(m1);
                        ulonglong2 r1 = *reinterpret_cast<const ulonglong2*>(m1 + 4);
                        ulonglong2 r2 = *reinterpret_cast<const ulonglong2*>(m1 + 8);
                        ulonglong2 r3 = *reinterpret_cast<const ulonglong2*>(m1 + 12);
                        unsigned long long r4 = *reinterpret_cast<const unsigned long long*>(m1 + 16);
                        O[0] = fma2(Y1, r0.x, O[0]); O[1] = fma2(Y1, r0.y, O[1]);
                        O[2] = fma2(Y1, r1.x, O[2]); O[3] = fma2(Y1, r1.y, O[3]);
                        O[4] = fma2(Y1, r2.x, O[4]); O[5] = fma2(Y1, r2.y, O[5]);
                        O[6] = fma2(Y1, r3.x, O[6]); O[7] = fma2(Y1, r3.y, O[7]);
                        O[8] = fma2(Y1, r4,   O[8]);
                    }
                }
            }
            float* op = out + ((size_t)(n * 64 + o) * TFULL + (t0 + t_loc)) * VD;
#pragma unroll
            for (int q = 0; q < 9; q++) {
                float a, b;
                upk2(O[q], a, b);
                *reinterpret_cast<float2*>(op + 2 * q) =
                    make_float2(fmaxf(a, 0.0f), fmaxf(b, 0.0f));
            }
        }

        // ---- pack next tile's A frags ----
        if (hasNext) {
#pragma unroll
            for (int u = 0; u < 16; u++) {
                int i = tid + u * THREADS;
                int c = i >> 7, pos = i & 127;
                if (pos < MROWS)
                    pack_A(smem + OFF_AH, smem + OFF_AL, c, pos, pf[u]);
            }
        }
        __syncthreads();
    }
}

extern "C" void kernel_launch(void* const* d_in, const int* in_sizes, int n_in,
                              void* d_out, int out_size)
{
    (void)in_sizes; (void)n_in; (void)out_size;
    const float* x    = (const float*)d_in[0];
    const float* A    = (const float*)d_in[1];
    const float* PA   = (const float*)d_in[2];
    const float* Wta  = (const float*)d_in[3];
    const float* bta  = (const float*)d_in[4];
    const float* g_ta = (const float*)d_in[5];
    const float* b_ta = (const float*)d_in[6];
    const float* m_ta = (const float*)d_in[7];
    const float* v_ta = (const float*)d_in[8];
    // d_in[9..12] dead attention branch
    const float* g_bn = (const float*)d_in[13];
    const float* b_bn = (const float*)d_in[14];
    const float* m_bn = (const float*)d_in[15];
    const float* v_bn = (const float*)d_in[16];
    float* out = (float*)d_out;

    cudaFuncSetAttribute(ctrgc_hmma5, cudaFuncAttributeMaxDynamicSharedMemorySize, SMEM_BYTES);

    prep_kernel<<<1, 256>>>(A, PA, Wta, bta, g_ta, b_ta, m_ta, v_ta,
                            g_bn, b_bn, m_bn, v_bn);
    ctrgc_hmma5<<<GRID, THREADS, SMEM_BYTES>>>(x, out);
}

// round 6
// speedup vs baseline: 2.0323x; 1.2961x over previous
#include <cuda_runtime.h>
#include <cuda_bf16.h>
#include <cstdint>

// ---------------------------------------------------------------------------
// CTRGC round 6: BOTH stages on tensor cores (mma.sync m16n8k16 bf16, 3-term
// split), zero scalar-fma stage B, bias folded into the GEMM as K-column 54.
//
// Stage A: Y[(k,o) 192 rows, pos=(t,v) 128 cols] = Weff[192,64c] * X[64c,128pos]
//   (A-operand = W row-major frags, B-operand = X col-major frags)
// Stage B: out[(t,o) 448 rows, w 24 cols] = Yr[(t,o), (k,v)+bias 64K] * M'[64K, 24]
//   D of stage A is repacked straight into stage-B A-fragments (bf16 hi/lo).
// ---------------------------------------------------------------------------

#define TFULL 256
#define CIN 64
#define VD 18
#define TT 7
#define TILES_PER_N 37
#define TILES_PER_CTA 32
#define THREADS 512
#define GRID 148

// ---- smem byte offsets ----
#define OFF_WAH 0                          // W A-frags hi: 12*4*32*16 = 24576
#define OFF_WAL (OFF_WAH + 12*4*32*16)
#define OFF_XBH (OFF_WAL + 12*4*32*16)     // X B-frags hi: 16*4*32*8 = 16384
#define OFF_XBL (OFF_XBH + 16*4*32*8)
#define OFF_YAH (OFF_XBL + 16*4*32*8)      // Y A-frags hi: 28*4*32*16 = 57344
#define OFF_YAL (OFF_YAH + 28*4*32*16)
#define OFF_MBH (OFF_YAL + 28*4*32*16)     // M' B-frags hi: 3*4*32*8 = 3072
#define OFF_MBL (OFF_MBH + 3*4*32*8)
#define SMEM_BYTES (OFF_MBL + 3*4*32*8)    // 202752

// prepped parameters (device globals)
__device__ uint4 d_WfH[12 * 4 * 32];
__device__ uint4 d_WfL[12 * 4 * 32];
__device__ unsigned long long d_MfH[3 * 4 * 32];
__device__ unsigned long long d_MfL[3 * 4 * 32];
__device__ float d_Cf[64];

__device__ __forceinline__ uint32_t pack2bf(float x, float y) {
    __nv_bfloat162 t = __floats2bfloat162_rn(x, y);   // x -> low half
    return *reinterpret_cast<uint32_t*>(&t);
}

// M'[kc][w]: kc<54 -> M_{kc/18}[kc%18][w]; kc==54 -> 1 (bias lane); else 0.
__device__ float mprime(const float* A, const float* PA, int kc, int w) {
    if (w >= VD) return 0.0f;
    if (kc < 54) {
        int k = kc / 18, v = kc - 18 * k;
        return A[(k * VD + v) * VD + w] + PA[(k * VD + v) * VD + w];
    }
    return (kc == 54) ? 1.0f : 0.0f;
}

__global__ void prep_kernel(const float* __restrict__ A, const float* __restrict__ PA,
                            const float* __restrict__ Wta, const float* __restrict__ bta,
                            const float* __restrict__ g_ta, const float* __restrict__ b_ta,
                            const float* __restrict__ m_ta, const float* __restrict__ v_ta,
                            const float* __restrict__ g_bn, const float* __restrict__ b_bn,
                            const float* __restrict__ m_bn, const float* __restrict__ v_bn)
{
    int tid = threadIdx.x;
    // ---- W A-fragments: rows (k,o) 192 = 12 strips, K = c (64, 4 ks) ----
    for (int idx = tid; idx < 12 * 4 * 32; idx += blockDim.x) {
        int strip = idx >> 7;
        int ks = (idx >> 5) & 3;
        int lane = idx & 31;
        int g = lane >> 2, tig = lane & 3;
        int c0 = ks * 16 + 2 * tig;
        float vals[8];   // (r0,c0)(r0,c0+1)(r1,c0)(r1,c0+1)(r0,c0+8)(r0,c0+9)(r1,c0+8)(r1,c0+9)
#pragma unroll
        for (int e = 0; e < 8; e++) {
            int row = strip * 16 + g + ((e >> 1) & 1) * 8;
            int c = c0 + (e & 1) + (e >> 2) * 8;
            int k = row >> 6, o = row & 63;
            float s2 = g_bn[o] * rsqrtf(v_bn[o] + 1e-5f);
            float s1 = g_ta[k * 64 + o] * rsqrtf(v_ta[k * 64 + o] + 1e-5f);
            vals[e] = s2 * s1 * Wta[(k * 64 + o) * 64 + c];
        }
        float hf[8], lf[8];
#pragma unroll
        for (int e = 0; e < 8; e++) {
            __nv_bfloat16 h = __float2bfloat16(vals[e]);
            hf[e] = __bfloat162float(h);
            lf[e] = vals[e] - hf[e];
        }
        d_WfH[idx] = make_uint4(pack2bf(hf[0], hf[1]), pack2bf(hf[2], hf[3]),
                                pack2bf(hf[4], hf[5]), pack2bf(hf[6], hf[7]));
        d_WfL[idx] = make_uint4(pack2bf(lf[0], lf[1]), pack2bf(lf[2], lf[3]),
                                pack2bf(lf[4], lf[5]), pack2bf(lf[6], lf[7]));
    }
    // ---- M' B-fragments: K = (k,v)+bias (64, 4 ks), N = w (24, 3 nb) ----
    for (int idx = tid; idx < 3 * 4 * 32; idx += blockDim.x) {
        int nb = idx >> 7;
        int ks = (idx >> 5) & 3;
        int lane = idx & 31;
        int g = lane >> 2, tig = lane & 3;
        int wcol = nb * 8 + g;
        int kc0 = ks * 16 + 2 * tig;
        float vals[4] = { mprime(A, PA, kc0, wcol),     mprime(A, PA, kc0 + 1, wcol),
                          mprime(A, PA, kc0 + 8, wcol), mprime(A, PA, kc0 + 9, wcol) };
        float hf[4], lf[4];
#pragma unroll
        for (int e = 0; e < 4; e++) {
            __nv_bfloat16 h = __float2bfloat16(vals[e]);
            hf[e] = __bfloat162float(h);
            lf[e] = vals[e] - hf[e];
        }
        d_MfH[idx] = ((unsigned long long)pack2bf(hf[2], hf[3]) << 32) | pack2bf(hf[0], hf[1]);
        d_MfL[idx] = ((unsigned long long)pack2bf(lf[2], lf[3]) << 32) | pack2bf(lf[0], lf[1]);
    }
    // ---- folded bias ----
    if (tid < 64) {
        int o = tid;
        float s2 = g_bn[o] * rsqrtf(v_bn[o] + 1e-5f);
        float acc = 0.0f;
        for (int k = 0; k < 3; k++) {
            float s1 = g_ta[k * 64 + o] * rsqrtf(v_ta[k * 64 + o] + 1e-5f);
            acc += s1 * (bta[k * 64 + o] - m_ta[k * 64 + o]) + b_ta[k * 64 + o];
        }
        d_Cf[o] = s2 * acc + b_bn[o] - m_bn[o] * s2;
    }
}

// ---- HMMA m16n8k16 bf16, f32 accum ----
__device__ __forceinline__ void mma_bf16(float* d, uint32_t a0, uint32_t a1,
                                         uint32_t a2, uint32_t a3,
                                         uint32_t b0, uint32_t b1) {
    asm("mma.sync.aligned.m16n8k16.row.col.f32.bf16.bf16.f32 "
        "{%0,%1,%2,%3},{%4,%5,%6,%7},{%8,%9},{%0,%1,%2,%3};"
        : "+f"(d[0]), "+f"(d[1]), "+f"(d[2]), "+f"(d[3])
        : "r"(a0), "r"(a1), "r"(a2), "r"(a3), "r"(b0), "r"(b1));
}

extern __shared__ char smem[];

// write one (row2, kcol even pair) bf16 hi/lo into stage-B A-frag buffers
__device__ __forceinline__ void ya_write(int row2, int kcol, float d0, float d1) {
    int strip2 = row2 >> 4, r2 = row2 & 15;
    int ks2 = kcol >> 4, cc2 = kcol & 15;
    int lane2 = (r2 & 7) * 4 + ((cc2 >> 1) & 3);
    int reg2 = (r2 >> 3) + 2 * (cc2 >> 3);
    int off = (((strip2 * 4 + ks2) * 32 + lane2) << 4) + reg2 * 4;
    __nv_bfloat16 h0 = __float2bfloat16(d0);
    __nv_bfloat16 h1 = __float2bfloat16(d1);
    float h0f = __bfloat162float(h0), h1f = __bfloat162float(h1);
    *reinterpret_cast<uint32_t*>(smem + OFF_YAH + off) = pack2bf(h0f, h1f);
    *reinterpret_cast<uint32_t*>(smem + OFF_YAL + off) = pack2bf(d0 - h0f, d1 - h1f);
}

__global__ __launch_bounds__(THREADS, 1)
void ctrgc6(const float* __restrict__ x, float* __restrict__ out)
{
    const int tid = threadIdx.x;
    const int w = tid >> 5;      // warp 0..15
    const int lane = tid & 31;
    const int g = lane >> 2;
    const int tig = lane & 3;

    // ---- one-time init ----
    {
        uint4* wh = reinterpret_cast<uint4*>(smem + OFF_WAH);
        uint4* wl = reinterpret_cast<uint4*>(smem + OFF_WAL);
        for (int i = tid; i < 12 * 4 * 32; i += THREADS) { wh[i] = d_WfH[i]; wl[i] = d_WfL[i]; }
        unsigned long long* mh = reinterpret_cast<unsigned long long*>(smem + OFF_MBH);
        unsigned long long* ml = reinterpret_cast<unsigned long long*>(smem + OFF_MBL);
        for (int i = tid; i < 3 * 4 * 32; i += THREADS) { mh[i] = d_MfH[i]; ml[i] = d_MfL[i]; }
        // zero YA (hi+lo): pad K-cols 55..63 must stay 0 forever
        uint32_t* ya = reinterpret_cast<uint32_t*>(smem + OFF_YAH);
        for (int i = tid; i < (2 * 28 * 4 * 32 * 16) / 4; i += THREADS) ya[i] = 0u;
    }
    __syncthreads();
    // bias column kcol=54: Y[row2][54] = Cf[o]  (pair (54,55), 55 stays 0)
    if (tid < 448) {
        float cf = d_Cf[tid & 63];
        ya_write(tid, 54, cf, 0.0f);
    }
    __syncthreads();

    const int tile0 = blockIdx.x * TILES_PER_CTA;

    // conversion lane constants: pos = w*8 + (lane>>2), c = ks*16 + reg*8 + 2*(lane&3)
    const int cv_pos = w * 8 + g;
    const int cv_cbase = 2 * tig;

    // ---- prologue: convert tile0 into X B-frags ----
    {
        int n = tile0 / TILES_PER_N;
        int j = tile0 - n * TILES_PER_N;
        int t0 = j * TT;
        int nvalid = ((t0 + TT <= TFULL) ? TT : (TFULL - t0)) * VD;
        const float* xb = x + (size_t)n * (CIN * TFULL * VD) + (size_t)t0 * VD;
#pragma unroll
        for (int u = 0; u < 8; u++) {
            int ks = u >> 1, reg = u & 1;
            int c0 = ks * 16 + reg * 8 + cv_cbase;
            float v0 = 0.0f, v1 = 0.0f;
            if (cv_pos < nvalid) {
                v0 = xb[c0 * (TFULL * VD) + cv_pos];
                v1 = xb[(c0 + 1) * (TFULL * VD) + cv_pos];
            }
            __nv_bfloat16 h0 = __float2bfloat16(v0), h1 = __float2bfloat16(v1);
            float h0f = __bfloat162float(h0), h1f = __bfloat162float(h1);
            int off = (((w * 4 + ks) * 32 + lane) << 3) + reg * 4;
            *reinterpret_cast<uint32_t*>(smem + OFF_XBH + off) = pack2bf(h0f, h1f);
            *reinterpret_cast<uint32_t*>(smem + OFF_XBL + off) = pack2bf(v0 - h0f, v1 - h1f);
        }
    }
    __syncthreads();

    for (int rel = 0; rel < TILES_PER_CTA; rel++) {
        const int tile = tile0 + rel;
        const int n  = tile / TILES_PER_N;
        const int j  = tile - n * TILES_PER_N;
        const int t0 = j * TT;
        const int valid_t = (t0 + TT <= TFULL) ? TT : (TFULL - t0);

        // ================== phase 1: stage A GEMM + repack into YA ==========
        {
            // hoist this warp's X B-frags (posblk = w)
            uint2 xbh[4], xbl[4];
#pragma unroll
            for (int ks = 0; ks < 4; ks++) {
                xbh[ks] = *reinterpret_cast<const uint2*>(
                    smem + OFF_XBH + (((w * 4 + ks) * 32 + lane) << 3));
                xbl[ks] = *reinterpret_cast<const uint2*>(
                    smem + OFF_XBL + (((w * 4 + ks) * 32 + lane) << 3));
            }
            const int p0 = w * 8 + 2 * tig;     // D col pair -> pos (C-frag mapping)
            const bool pok = (p0 < 126);
            int tloc = (p0 * 228) >> 12;
            int vloc = p0 - 18 * tloc;

#pragma unroll
            for (int s = 0; s < 12; s++) {
                float D[4] = {0.0f, 0.0f, 0.0f, 0.0f};
#pragma unroll
                for (int ks = 0; ks < 4; ks++) {
                    uint4 ah = *reinterpret_cast<const uint4*>(
                        smem + OFF_WAH + (((s * 4 + ks) * 32 + lane) << 4));
                    uint4 al = *reinterpret_cast<const uint4*>(
                        smem + OFF_WAL + (((s * 4 + ks) * 32 + lane) << 4));
                    mma_bf16(D, ah.x, ah.y, ah.z, ah.w, xbh[ks].x, xbh[ks].y);
                    mma_bf16(D, ah.x, ah.y, ah.z, ah.w, xbl[ks].x, xbl[ks].y);
                    mma_bf16(D, al.x, al.y, al.z, al.w, xbh[ks].x, xbh[ks].y);
                }
                if (pok) {
                    int rowA = s * 16 + g;                 // (k,o) row
                    int k = rowA >> 6, o = rowA & 63;
                    int kcol = k * 18 + vloc;
                    ya_write(tloc * 64 + o, kcol, D[0], D[1]);
                    rowA += 8;
                    k = rowA >> 6; o = rowA & 63;
                    kcol = k * 18 + vloc;
                    ya_write(tloc * 64 + o, kcol, D[2], D[3]);
                }
            }
        }
        __syncthreads();

        // ====== phase 2: LDG(next) | stage B GEMM + relu/store | STS(next) ==
        const bool hasNext = (rel + 1 < TILES_PER_CTA);
        float pf[16];
        int nxt_nvalid = 0;
        if (hasNext) {
            int tn = tile + 1;
            int nn = tn / TILES_PER_N;
            int jn = tn - nn * TILES_PER_N;
            int tn0 = jn * TT;
            nxt_nvalid = ((tn0 + TT <= TFULL) ? TT : (TFULL - tn0)) * VD;
            const float* xb = x + (size_t)nn * (CIN * TFULL * VD) + (size_t)tn0 * VD;
#pragma unroll
            for (int u = 0; u < 8; u++) {
                int ks = u >> 1, reg = u & 1;
                int c0 = ks * 16 + reg * 8 + cv_cbase;
                bool okp = (cv_pos < nxt_nvalid);
                pf[2 * u]     = okp ? __ldg(xb + c0 * (TFULL * VD) + cv_pos) : 0.0f;
                pf[2 * u + 1] = okp ? __ldg(xb + (c0 + 1) * (TFULL * VD) + cv_pos) : 0.0f;
            }
        }

        // ---- stage B: warps own strips {w, w+16} of 28 ----
        for (int si = w; si < 28; si += 16) {
            uint4 ah[4], al[4];
#pragma unroll
            for (int ks = 0; ks < 4; ks++) {
                ah[ks] = *reinterpret_cast<const uint4*>(
                    smem + OFF_YAH + (((si * 4 + ks) * 32 + lane) << 4));
                al[ks] = *reinterpret_cast<const uint4*>(
                    smem + OFF_YAL + (((si * 4 + ks) * 32 + lane) << 4));
            }
            const int rowB = si * 16 + g;
            const int tB = rowB >> 6;          // = si>>2
            const int oB = rowB & 63;
#pragma unroll
            for (int nb = 0; nb < 3; nb++) {
                float D2[4] = {0.0f, 0.0f, 0.0f, 0.0f};
#pragma unroll
                for (int ks = 0; ks < 4; ks++) {
                    uint2 bh = *reinterpret_cast<const uint2*>(
                        smem + OFF_MBH + (((nb * 4 + ks) * 32 + lane) << 3));
                    uint2 bl = *reinterpret_cast<const uint2*>(
                        smem + OFF_MBL + (((nb * 4 + ks) * 32 + lane) << 3));
                    mma_bf16(D2, ah[ks].x, ah[ks].y, ah[ks].z, ah[ks].w, bh.x, bh.y);
                    mma_bf16(D2, ah[ks].x, ah[ks].y, ah[ks].z, ah[ks].w, bl.x, bl.y);
                    mma_bf16(D2, al[ks].x, al[ks].y, al[ks].z, al[ks].w, bh.x, bh.y);
                }
                int w0 = nb * 8 + 2 * tig;
                if (w0 < VD && tB < valid_t) {
                    size_t base = ((size_t)(n * 64 + oB) * TFULL + (t0 + tB)) * VD + w0;
                    *reinterpret_cast<float2*>(out + base) =
                        make_float2(fmaxf(D2[0], 0.0f), fmaxf(D2[1], 0.0f));
                    size_t base2 = base + (size_t)8 * TFULL * VD;   // o+8, same t
                    *reinterpret_cast<float2*>(out + base2) =
                        make_float2(fmaxf(D2[2], 0.0f), fmaxf(D2[3], 0.0f));
                }
            }
        }

        // ---- convert next tile into X B-frags ----
        if (hasNext) {
#pragma unroll
            for (int u = 0; u < 8; u++) {
                int ks = u >> 1, reg = u & 1;
                float v0 = pf[2 * u], v1 = pf[2 * u + 1];
                __nv_bfloat16 h0 = __float2bfloat16(v0), h1 = __float2bfloat16(v1);
                float h0f = __bfloat162float(h0), h1f = __bfloat162float(h1);
                int off = (((w * 4 + ks) * 32 + lane) << 3) + reg * 4;
                *reinterpret_cast<uint32_t*>(smem + OFF_XBH + off) = pack2bf(h0f, h1f);
                *reinterpret_cast<uint32_t*>(smem + OFF_XBL + off) = pack2bf(v0 - h0f, v1 - h1f);
            }
        }
        __syncthreads();
    }
}

extern "C" void kernel_launch(void* const* d_in, const int* in_sizes, int n_in,
                              void* d_out, int out_size)
{
    (void)in_sizes; (void)n_in; (void)out_size;
    const float* x    = (const float*)d_in[0];
    const float* A    = (const float*)d_in[1];
    const float* PA   = (const float*)d_in[2];
    const float* Wta  = (const float*)d_in[3];
    const float* bta  = (const float*)d_in[4];
    const float* g_ta = (const float*)d_in[5];
    const float* b_ta = (const float*)d_in[6];
    const float* m_ta = (const float*)d_in[7];
    const float* v_ta = (const float*)d_in[8];
    // d_in[9..12] dead attention branch
    const float* g_bn = (const float*)d_in[13];
    const float* b_bn = (const float*)d_in[14];
    const float* m_bn = (const float*)d_in[15];
    const float* v_bn = (const float*)d_in[16];
    float* out = (float*)d_out;

    cudaFuncSetAttribute(ctrgc6, cudaFuncAttributeMaxDynamicSharedMemorySize, SMEM_BYTES);

    prep_kernel<<<1, 256>>>(A, PA, Wta, bta, g_ta, b_ta, m_ta, v_ta,
                            g_bn, b_bn, m_bn, v_bn);
    ctrgc6<<<GRID, THREADS, SMEM_BYTES>>>(x, out);
}

// round 7
// speedup vs baseline: 2.5318x; 1.2458x over previous
#include <cuda_runtime.h>
#include <cuda_bf16.h>
#include <cstdint>

// ---------------------------------------------------------------------------
// CTRGC round 7: round-6 dual-GEMM dataflow + 4x4 warp blocking in stage A
// (W frags read by 4 warps instead of 16) and M' frags hoisted to registers
// in stage B. Pure LSU-traffic reduction; MMA schedule unchanged.
// ---------------------------------------------------------------------------

#define TFULL 256
#define CIN 64
#define VD 18
#define TT 7
#define TILES_PER_N 37
#define TILES_PER_CTA 32
#define THREADS 512
#define GRID 148

// ---- smem byte offsets ----
#define OFF_WAH 0                          // W A-frags hi: 12*4*32*16 = 24576
#define OFF_WAL (OFF_WAH + 12*4*32*16)
#define OFF_XBH (OFF_WAL + 12*4*32*16)     // X B-frags hi: 16*4*32*8 = 16384
#define OFF_XBL (OFF_XBH + 16*4*32*8)
#define OFF_YAH (OFF_XBL + 16*4*32*8)      // Y A-frags hi: 28*4*32*16 = 57344
#define OFF_YAL (OFF_YAH + 28*4*32*16)
#define OFF_MBH (OFF_YAL + 28*4*32*16)     // M' B-frags hi: 3*4*32*8 = 3072
#define OFF_MBL (OFF_MBH + 3*4*32*8)
#define SMEM_BYTES (OFF_MBL + 3*4*32*8)    // 202752

// prepped parameters (device globals)
__device__ uint4 d_WfH[12 * 4 * 32];
__device__ uint4 d_WfL[12 * 4 * 32];
__device__ unsigned long long d_MfH[3 * 4 * 32];
__device__ unsigned long long d_MfL[3 * 4 * 32];
__device__ float d_Cf[64];

__device__ __forceinline__ uint32_t pack2bf(float x, float y) {
    __nv_bfloat162 t = __floats2bfloat162_rn(x, y);   // x -> low half
    return *reinterpret_cast<uint32_t*>(&t);
}

// M'[kc][w]: kc<54 -> M_{kc/18}[kc%18][w]; kc==54 -> 1 (bias lane); else 0.
__device__ float mprime(const float* A, const float* PA, int kc, int w) {
    if (w >= VD) return 0.0f;
    if (kc < 54) {
        int k = kc / 18, v = kc - 18 * k;
        return A[(k * VD + v) * VD + w] + PA[(k * VD + v) * VD + w];
    }
    return (kc == 54) ? 1.0f : 0.0f;
}

__global__ void prep_kernel(const float* __restrict__ A, const float* __restrict__ PA,
                            const float* __restrict__ Wta, const float* __restrict__ bta,
                            const float* __restrict__ g_ta, const float* __restrict__ b_ta,
                            const float* __restrict__ m_ta, const float* __restrict__ v_ta,
                            const float* __restrict__ g_bn, const float* __restrict__ b_bn,
                            const float* __restrict__ m_bn, const float* __restrict__ v_bn)
{
    int tid = threadIdx.x;
    // ---- W A-fragments: rows (k,o) 192 = 12 strips, K = c (64, 4 ks) ----
    for (int idx = tid; idx < 12 * 4 * 32; idx += blockDim.x) {
        int strip = idx >> 7;
        int ks = (idx >> 5) & 3;
        int lane = idx & 31;
        int g = lane >> 2, tig = lane & 3;
        int c0 = ks * 16 + 2 * tig;
        float vals[8];
#pragma unroll
        for (int e = 0; e < 8; e++) {
            int row = strip * 16 + g + ((e >> 1) & 1) * 8;
            int c = c0 + (e & 1) + (e >> 2) * 8;
            int k = row >> 6, o = row & 63;
            float s2 = g_bn[o] * rsqrtf(v_bn[o] + 1e-5f);
            float s1 = g_ta[k * 64 + o] * rsqrtf(v_ta[k * 64 + o] + 1e-5f);
            vals[e] = s2 * s1 * Wta[(k * 64 + o) * 64 + c];
        }
        float hf[8], lf[8];
#pragma unroll
        for (int e = 0; e < 8; e++) {
            __nv_bfloat16 h = __float2bfloat16(vals[e]);
            hf[e] = __bfloat162float(h);
            lf[e] = vals[e] - hf[e];
        }
        d_WfH[idx] = make_uint4(pack2bf(hf[0], hf[1]), pack2bf(hf[2], hf[3]),
                                pack2bf(hf[4], hf[5]), pack2bf(hf[6], hf[7]));
        d_WfL[idx] = make_uint4(pack2bf(lf[0], lf[1]), pack2bf(lf[2], lf[3]),
                                pack2bf(lf[4], lf[5]), pack2bf(lf[6], lf[7]));
    }
    // ---- M' B-fragments ----
    for (int idx = tid; idx < 3 * 4 * 32; idx += blockDim.x) {
        int nb = idx >> 7;
        int ks = (idx >> 5) & 3;
        int lane = idx & 31;
        int g = lane >> 2, tig = lane & 3;
        int wcol = nb * 8 + g;
        int kc0 = ks * 16 + 2 * tig;
        float vals[4] = { mprime(A, PA, kc0, wcol),     mprime(A, PA, kc0 + 1, wcol),
                          mprime(A, PA, kc0 + 8, wcol), mprime(A, PA, kc0 + 9, wcol) };
        float hf[4], lf[4];
#pragma unroll
        for (int e = 0; e < 4; e++) {
            __nv_bfloat16 h = __float2bfloat16(vals[e]);
            hf[e] = __bfloat162float(h);
            lf[e] = vals[e] - hf[e];
        }
        d_MfH[idx] = ((unsigned long long)pack2bf(hf[2], hf[3]) << 32) | pack2bf(hf[0], hf[1]);
        d_MfL[idx] = ((unsigned long long)pack2bf(lf[2], lf[3]) << 32) | pack2bf(lf[0], lf[1]);
    }
    // ---- folded bias ----
    if (tid < 64) {
        int o = tid;
        float s2 = g_bn[o] * rsqrtf(v_bn[o] + 1e-5f);
        float acc = 0.0f;
        for (int k = 0; k < 3; k++) {
            float s1 = g_ta[k * 64 + o] * rsqrtf(v_ta[k * 64 + o] + 1e-5f);
            acc += s1 * (bta[k * 64 + o] - m_ta[k * 64 + o]) + b_ta[k * 64 + o];
        }
        d_Cf[o] = s2 * acc + b_bn[o] - m_bn[o] * s2;
    }
}

// ---- HMMA m16n8k16 bf16, f32 accum ----
__device__ __forceinline__ void mma_bf16(float* d, uint32_t a0, uint32_t a1,
                                         uint32_t a2, uint32_t a3,
                                         uint32_t b0, uint32_t b1) {
    asm("mma.sync.aligned.m16n8k16.row.col.f32.bf16.bf16.f32 "
        "{%0,%1,%2,%3},{%4,%5,%6,%7},{%8,%9},{%0,%1,%2,%3};"
        : "+f"(d[0]), "+f"(d[1]), "+f"(d[2]), "+f"(d[3])
        : "r"(a0), "r"(a1), "r"(a2), "r"(a3), "r"(b0), "r"(b1));
}

extern __shared__ char smem[];

// write one (row2, kcol even pair) bf16 hi/lo into stage-B A-frag buffers
__device__ __forceinline__ void ya_write(int row2, int kcol, float d0, float d1) {
    int strip2 = row2 >> 4, r2 = row2 & 15;
    int ks2 = kcol >> 4, cc2 = kcol & 15;
    int lane2 = (r2 & 7) * 4 + ((cc2 >> 1) & 3);
    int reg2 = (r2 >> 3) + 2 * (cc2 >> 3);
    int off = (((strip2 * 4 + ks2) * 32 + lane2) << 4) + reg2 * 4;
    __nv_bfloat16 h0 = __float2bfloat16(d0);
    __nv_bfloat16 h1 = __float2bfloat16(d1);
    float h0f = __bfloat162float(h0), h1f = __bfloat162float(h1);
    *reinterpret_cast<uint32_t*>(smem + OFF_YAH + off) = pack2bf(h0f, h1f);
    *reinterpret_cast<uint32_t*>(smem + OFF_YAL + off) = pack2bf(d0 - h0f, d1 - h1f);
}

__global__ __launch_bounds__(THREADS, 1)
void ctrgc7(const float* __restrict__ x, float* __restrict__ out)
{
    const int tid = threadIdx.x;
    const int w = tid >> 5;      // warp 0..15
    const int lane = tid & 31;
    const int g = lane >> 2;
    const int tig = lane & 3;

    // ---- one-time init ----
    {
        uint4* wh = reinterpret_cast<uint4*>(smem + OFF_WAH);
        uint4* wl = reinterpret_cast<uint4*>(smem + OFF_WAL);
        for (int i = tid; i < 12 * 4 * 32; i += THREADS) { wh[i] = d_WfH[i]; wl[i] = d_WfL[i]; }
        unsigned long long* mh = reinterpret_cast<unsigned long long*>(smem + OFF_MBH);
        unsigned long long* ml = reinterpret_cast<unsigned long long*>(smem + OFF_MBL);
        for (int i = tid; i < 3 * 4 * 32; i += THREADS) { mh[i] = d_MfH[i]; ml[i] = d_MfL[i]; }
        uint32_t* ya = reinterpret_cast<uint32_t*>(smem + OFF_YAH);
        for (int i = tid; i < (2 * 28 * 4 * 32 * 16) / 4; i += THREADS) ya[i] = 0u;
    }
    __syncthreads();
    // bias column kcol=54: Y[row2][54] = Cf[o]  (pair (54,55), 55 stays 0)
    if (tid < 448) {
        float cf = d_Cf[tid & 63];
        ya_write(tid, 54, cf, 0.0f);
    }
    __syncthreads();

    const int tile0 = blockIdx.x * TILES_PER_CTA;

    // conversion lane constants
    const int cv_pos = w * 8 + g;
    const int cv_cbase = 2 * tig;

    // ---- prologue: convert tile0 into X B-frags ----
    {
        int n = tile0 / TILES_PER_N;
        int j = tile0 - n * TILES_PER_N;
        int t0 = j * TT;
        int nvalid = ((t0 + TT <= TFULL) ? TT : (TFULL - t0)) * VD;
        const float* xb = x + (size_t)n * (CIN * TFULL * VD) + (size_t)t0 * VD;
#pragma unroll
        for (int u = 0; u < 8; u++) {
            int ks = u >> 1, reg = u & 1;
            int c0 = ks * 16 + reg * 8 + cv_cbase;
            float v0 = 0.0f, v1 = 0.0f;
            if (cv_pos < nvalid) {
                v0 = xb[c0 * (TFULL * VD) + cv_pos];
                v1 = xb[(c0 + 1) * (TFULL * VD) + cv_pos];
            }
            __nv_bfloat16 h0 = __float2bfloat16(v0), h1 = __float2bfloat16(v1);
            float h0f = __bfloat162float(h0), h1f = __bfloat162float(h1);
            int off = (((w * 4 + ks) * 32 + lane) << 3) + reg * 4;
            *reinterpret_cast<uint32_t*>(smem + OFF_XBH + off) = pack2bf(h0f, h1f);
            *reinterpret_cast<uint32_t*>(smem + OFF_XBL + off) = pack2bf(v0 - h0f, v1 - h1f);
        }
    }
    __syncthreads();

    for (int rel = 0; rel < TILES_PER_CTA; rel++) {
        const int tile = tile0 + rel;
        const int n  = tile / TILES_PER_N;
        const int j  = tile - n * TILES_PER_N;
        const int t0 = j * TT;
        const int valid_t = (t0 + TT <= TFULL) ? TT : (TFULL - t0);

        // ============ phase 1: stage A GEMM (4x4 blocking) + repack ==========
        {
            const int sg = w >> 2;   // strip group: strips {sg, sg+4, sg+8}
            const int pg = w & 3;    // posblk group: {pg, pg+4, pg+8, pg+12}

            // hoist X B-frags for this warp's 4 posblks (64 regs)
            uint2 xbh[4][4], xbl[4][4];
#pragma unroll
            for (int p_i = 0; p_i < 4; p_i++) {
                int pb = pg + 4 * p_i;
#pragma unroll
                for (int ks = 0; ks < 4; ks++) {
                    xbh[p_i][ks] = *reinterpret_cast<const uint2*>(
                        smem + OFF_XBH + (((pb * 4 + ks) * 32 + lane) << 3));
                    xbl[p_i][ks] = *reinterpret_cast<const uint2*>(
                        smem + OFF_XBL + (((pb * 4 + ks) * 32 + lane) << 3));
                }
            }
#pragma unroll
            for (int s_i = 0; s_i < 3; s_i++) {
                const int s = sg + 4 * s_i;
                uint4 ah[4], al[4];
#pragma unroll
                for (int ks = 0; ks < 4; ks++) {
                    ah[ks] = *reinterpret_cast<const uint4*>(
                        smem + OFF_WAH + (((s * 4 + ks) * 32 + lane) << 4));
                    al[ks] = *reinterpret_cast<const uint4*>(
                        smem + OFF_WAL + (((s * 4 + ks) * 32 + lane) << 4));
                }
                const int rowA0 = s * 16 + g;
                const int k0 = rowA0 >> 6, o0 = rowA0 & 63;
                const int rowA1 = rowA0 + 8;
                const int k1 = rowA1 >> 6, o1 = rowA1 & 63;
#pragma unroll
                for (int p_i = 0; p_i < 4; p_i++) {
                    const int pb = pg + 4 * p_i;
                    const int p0 = pb * 8 + 2 * tig;
                    float D[4] = {0.0f, 0.0f, 0.0f, 0.0f};
#pragma unroll
                    for (int ks = 0; ks < 4; ks++) {
                        mma_bf16(D, ah[ks].x, ah[ks].y, ah[ks].z, ah[ks].w,
                                 xbh[p_i][ks].x, xbh[p_i][ks].y);
                        mma_bf16(D, ah[ks].x, ah[ks].y, ah[ks].z, ah[ks].w,
                                 xbl[p_i][ks].x, xbl[p_i][ks].y);
                        mma_bf16(D, al[ks].x, al[ks].y, al[ks].z, al[ks].w,
                                 xbh[p_i][ks].x, xbh[p_i][ks].y);
                    }
                    if (p0 < 126) {
                        int tloc = (p0 * 228) >> 12;
                        int vloc = p0 - 18 * tloc;
                        ya_write(tloc * 64 + o0, k0 * 18 + vloc, D[0], D[1]);
                        ya_write(tloc * 64 + o1, k1 * 18 + vloc, D[2], D[3]);
                    }
                }
            }
        }
        __syncthreads();

        // ====== phase 2: LDG(next) | stage B GEMM + relu/store | STS(next) ==
        const bool hasNext = (rel + 1 < TILES_PER_CTA);
        float pf[16];
        int nxt_nvalid = 0;
        if (hasNext) {
            int tn = tile + 1;
            int nn = tn / TILES_PER_N;
            int jn = tn - nn * TILES_PER_N;
            int tn0 = jn * TT;
            nxt_nvalid = ((tn0 + TT <= TFULL) ? TT : (TFULL - tn0)) * VD;
            const float* xb = x + (size_t)nn * (CIN * TFULL * VD) + (size_t)tn0 * VD;
#pragma unroll
            for (int u = 0; u < 8; u++) {
                int ks = u >> 1, reg = u & 1;
                int c0 = ks * 16 + reg * 8 + cv_cbase;
                bool okp = (cv_pos < nxt_nvalid);
                pf[2 * u]     = okp ? __ldg(xb + c0 * (TFULL * VD) + cv_pos) : 0.0f;
                pf[2 * u + 1] = okp ? __ldg(xb + (c0 + 1) * (TFULL * VD) + cv_pos) : 0.0f;
            }
        }

        // ---- stage B: M' frags hoisted once (48 regs), strips {w, w+16} ----
        {
            uint2 mbh[3][4], mbl[3][4];
#pragma unroll
            for (int nb = 0; nb < 3; nb++)
#pragma unroll
                for (int ks = 0; ks < 4; ks++) {
                    mbh[nb][ks] = *reinterpret_cast<const uint2*>(
                        smem + OFF_MBH + (((nb * 4 + ks) * 32 + lane) << 3));
                    mbl[nb][ks] = *reinterpret_cast<const uint2*>(
                        smem + OFF_MBL + (((nb * 4 + ks) * 32 + lane) << 3));
                }
            for (int si = w; si < 28; si += 16) {
                uint4 ah[4], al[4];
#pragma unroll
                for (int ks = 0; ks < 4; ks++) {
                    ah[ks] = *reinterpret_cast<const uint4*>(
                        smem + OFF_YAH + (((si * 4 + ks) * 32 + lane) << 4));
                    al[ks] = *reinterpret_cast<const uint4*>(
                        smem + OFF_YAL + (((si * 4 + ks) * 32 + lane) << 4));
                }
                const int rowB = si * 16 + g;
                const int tB = rowB >> 6;
                const int oB = rowB & 63;
#pragma unroll
                for (int nb = 0; nb < 3; nb++) {
                    float D2[4] = {0.0f, 0.0f, 0.0f, 0.0f};
#pragma unroll
                    for (int ks = 0; ks < 4; ks++) {
                        mma_bf16(D2, ah[ks].x, ah[ks].y, ah[ks].z, ah[ks].w,
                                 mbh[nb][ks].x, mbh[nb][ks].y);
                        mma_bf16(D2, ah[ks].x, ah[ks].y, ah[ks].z, ah[ks].w,
                                 mbl[nb][ks].x, mbl[nb][ks].y);
                        mma_bf16(D2, al[ks].x, al[ks].y, al[ks].z, al[ks].w,
                                 mbh[nb][ks].x, mbh[nb][ks].y);
                    }
                    int w0 = nb * 8 + 2 * tig;
                    if (w0 < VD && tB < valid_t) {
                        size_t base = ((size_t)(n * 64 + oB) * TFULL + (t0 + tB)) * VD + w0;
                        *reinterpret_cast<float2*>(out + base) =
                            make_float2(fmaxf(D2[0], 0.0f), fmaxf(D2[1], 0.0f));
                        size_t base2 = base + (size_t)8 * TFULL * VD;   // o+8
                        *reinterpret_cast<float2*>(out + base2) =
                            make_float2(fmaxf(D2[2], 0.0f), fmaxf(D2[3], 0.0f));
                    }
                }
            }
        }

        // ---- convert next tile into X B-frags ----
        if (hasNext) {
#pragma unroll
            for (int u = 0; u < 8; u++) {
                int ks = u >> 1, reg = u & 1;
                float v0 = pf[2 * u], v1 = pf[2 * u + 1];
                __nv_bfloat16 h0 = __float2bfloat16(v0), h1 = __float2bfloat16(v1);
                float h0f = __bfloat162float(h0), h1f = __bfloat162float(h1);
                int off = (((w * 4 + ks) * 32 + lane) << 3) + reg * 4;
                *reinterpret_cast<uint32_t*>(smem + OFF_XBH + off) = pack2bf(h0f, h1f);
                *reinterpret_cast<uint32_t*>(smem + OFF_XBL + off) = pack2bf(v0 - h0f, v1 - h1f);
            }
        }
        __syncthreads();
    }
}

extern "C" void kernel_launch(void* const* d_in, const int* in_sizes, int n_in,
                              void* d_out, int out_size)
{
    (void)in_sizes; (void)n_in; (void)out_size;
    const float* x    = (const float*)d_in[0];
    const float* A    = (const float*)d_in[1];
    const float* PA   = (const float*)d_in[2];
    const float* Wta  = (const float*)d_in[3];
    const float* bta  = (const float*)d_in[4];
    const float* g_ta = (const float*)d_in[5];
    const float* b_ta = (const float*)d_in[6];
    const float* m_ta = (const float*)d_in[7];
    const float* v_ta = (const float*)d_in[8];
    // d_in[9..12] dead attention branch
    const float* g_bn = (const float*)d_in[13];
    const float* b_bn = (const float*)d_in[14];
    const float* m_bn = (const float*)d_in[15];
    const float* v_bn = (const float*)d_in[16];
    float* out = (float*)d_out;

    cudaFuncSetAttribute(ctrgc7, cudaFuncAttributeMaxDynamicSharedMemorySize, SMEM_BYTES);

    prep_kernel<<<1, 256>>>(A, PA, Wta, bta, g_ta, b_ta, m_ta, v_ta,
                            g_bn, b_bn, m_bn, v_bn);
    ctrgc7<<<GRID, THREADS, SMEM_BYTES>>>(x, out);
}

// round 8
// speedup vs baseline: 2.6515x; 1.0473x over previous
#include <cuda_runtime.h>
#include <cuda_bf16.h>
#include <cstdint>

// ---------------------------------------------------------------------------
// CTRGC round 8: round-7 dual-GEMM + SoA-by-register fragment buffers for
// YA (stage-B A-frags) and XB (stage-A B-frags) -> all STS conflict-free.
// Reads switch LDS.128 -> 4x LDS.32 (same crossbar cycles, more issue slots).
// ---------------------------------------------------------------------------

#define TFULL 256
#define CIN 64
#define VD 18
#define TT 7
#define TILES_PER_N 37
#define TILES_PER_CTA 32
#define THREADS 512
#define GRID 148

// ---- smem byte offsets ----
#define OFF_WAH 0                          // W A-frags hi: 12*4*32*16 = 24576
#define OFF_WAL (OFF_WAH + 12*4*32*16)
#define OFF_XBH (OFF_WAL + 12*4*32*16)     // X B-frags hi (SoA): 16*4*2*32*4 = 16384
#define OFF_XBL (OFF_XBH + 16*4*2*32*4)
#define OFF_YAH (OFF_XBL + 16*4*2*32*4)    // Y A-frags hi (SoA): 28*4*4*32*4 = 57344
#define OFF_YAL (OFF_YAH + 28*4*4*32*4)
#define OFF_MBH (OFF_YAL + 28*4*4*32*4)    // M' B-frags hi: 3*4*32*8 = 3072
#define OFF_MBL (OFF_MBH + 3*4*32*8)
#define SMEM_BYTES (OFF_MBL + 3*4*32*8)    // 202752

// prepped parameters (device globals)
__device__ uint4 d_WfH[12 * 4 * 32];
__device__ uint4 d_WfL[12 * 4 * 32];
__device__ unsigned long long d_MfH[3 * 4 * 32];
__device__ unsigned long long d_MfL[3 * 4 * 32];
__device__ float d_Cf[64];

__device__ __forceinline__ uint32_t pack2bf(float x, float y) {
    __nv_bfloat162 t = __floats2bfloat162_rn(x, y);   // x -> low half
    return *reinterpret_cast<uint32_t*>(&t);
}

// M'[kc][w]: kc<54 -> M_{kc/18}[kc%18][w]; kc==54 -> 1 (bias lane); else 0.
__device__ float mprime(const float* A, const float* PA, int kc, int w) {
    if (w >= VD) return 0.0f;
    if (kc < 54) {
        int k = kc / 18, v = kc - 18 * k;
        return A[(k * VD + v) * VD + w] + PA[(k * VD + v) * VD + w];
    }
    return (kc == 54) ? 1.0f : 0.0f;
}

__global__ void prep_kernel(const float* __restrict__ A, const float* __restrict__ PA,
                            const float* __restrict__ Wta, const float* __restrict__ bta,
                            const float* __restrict__ g_ta, const float* __restrict__ b_ta,
                            const float* __restrict__ m_ta, const float* __restrict__ v_ta,
                            const float* __restrict__ g_bn, const float* __restrict__ b_bn,
                            const float* __restrict__ m_bn, const float* __restrict__ v_bn)
{
    int tid = threadIdx.x;
    // ---- W A-fragments: rows (k,o) 192 = 12 strips, K = c (64, 4 ks) ----
    for (int idx = tid; idx < 12 * 4 * 32; idx += blockDim.x) {
        int strip = idx >> 7;
        int ks = (idx >> 5) & 3;
        int lane = idx & 31;
        int g = lane >> 2, tig = lane & 3;
        int c0 = ks * 16 + 2 * tig;
        float vals[8];
#pragma unroll
        for (int e = 0; e < 8; e++) {
            int row = strip * 16 + g + ((e >> 1) & 1) * 8;
            int c = c0 + (e & 1) + (e >> 2) * 8;
            int k = row >> 6, o = row & 63;
            float s2 = g_bn[o] * rsqrtf(v_bn[o] + 1e-5f);
            float s1 = g_ta[k * 64 + o] * rsqrtf(v_ta[k * 64 + o] + 1e-5f);
            vals[e] = s2 * s1 * Wta[(k * 64 + o) * 64 + c];
        }
        float hf[8], lf[8];
#pragma unroll
        for (int e = 0; e < 8; e++) {
            __nv_bfloat16 h = __float2bfloat16(vals[e]);
            hf[e] = __bfloat162float(h);
            lf[e] = vals[e] - hf[e];
        }
        d_WfH[idx] = make_uint4(pack2bf(hf[0], hf[1]), pack2bf(hf[2], hf[3]),
                                pack2bf(hf[4], hf[5]), pack2bf(hf[6], hf[7]));
        d_WfL[idx] = make_uint4(pack2bf(lf[0], lf[1]), pack2bf(lf[2], lf[3]),
                                pack2bf(lf[4], lf[5]), pack2bf(lf[6], lf[7]));
    }
    // ---- M' B-fragments ----
    for (int idx = tid; idx < 3 * 4 * 32; idx += blockDim.x) {
        int nb = idx >> 7;
        int ks = (idx >> 5) & 3;
        int lane = idx & 31;
        int g = lane >> 2, tig = lane & 3;
        int wcol = nb * 8 + g;
        int kc0 = ks * 16 + 2 * tig;
        float vals[4] = { mprime(A, PA, kc0, wcol),     mprime(A, PA, kc0 + 1, wcol),
                          mprime(A, PA, kc0 + 8, wcol), mprime(A, PA, kc0 + 9, wcol) };
        float hf[4], lf[4];
#pragma unroll
        for (int e = 0; e < 4; e++) {
            __nv_bfloat16 h = __float2bfloat16(vals[e]);
            hf[e] = __bfloat162float(h);
            lf[e] = vals[e] - hf[e];
        }
        d_MfH[idx] = ((unsigned long long)pack2bf(hf[2], hf[3]) << 32) | pack2bf(hf[0], hf[1]);
        d_MfL[idx] = ((unsigned long long)pack2bf(lf[2], lf[3]) << 32) | pack2bf(lf[0], lf[1]);
    }
    // ---- folded bias ----
    if (tid < 64) {
        int o = tid;
        float s2 = g_bn[o] * rsqrtf(v_bn[o] + 1e-5f);
        float acc = 0.0f;
        for (int k = 0; k < 3; k++) {
            float s1 = g_ta[k * 64 + o] * rsqrtf(v_ta[k * 64 + o] + 1e-5f);
            acc += s1 * (bta[k * 64 + o] - m_ta[k * 64 + o]) + b_ta[k * 64 + o];
        }
        d_Cf[o] = s2 * acc + b_bn[o] - m_bn[o] * s2;
    }
}

// ---- HMMA m16n8k16 bf16, f32 accum ----
__device__ __forceinline__ void mma_bf16(float* d, uint32_t a0, uint32_t a1,
                                         uint32_t a2, uint32_t a3,
                                         uint32_t b0, uint32_t b1) {
    asm("mma.sync.aligned.m16n8k16.row.col.f32.bf16.bf16.f32 "
        "{%0,%1,%2,%3},{%4,%5,%6,%7},{%8,%9},{%0,%1,%2,%3};"
        : "+f"(d[0]), "+f"(d[1]), "+f"(d[2]), "+f"(d[3])
        : "r"(a0), "r"(a1), "r"(a2), "r"(a3), "r"(b0), "r"(b1));
}

extern __shared__ char smem[];

// SoA word address helpers (byte offsets)
// YA: word = ((frag*4 + reg) * 32 + lane) ; frag = strip2*4 + ks2
__device__ __forceinline__ int ya_off(int frag, int reg, int lane) {
    return (((frag * 4 + reg) * 32) + lane) * 4;
}
// XB: word = ((frag*2 + reg) * 32 + lane) ; frag = pb*4 + ks
__device__ __forceinline__ int xb_off(int frag, int reg, int lane) {
    return (((frag * 2 + reg) * 32) + lane) * 4;
}

// write one (row2, kcol even pair) bf16 hi/lo into stage-B A-frag buffers
__device__ __forceinline__ void ya_write(int row2, int kcol, float d0, float d1) {
    int strip2 = row2 >> 4, r2 = row2 & 15;
    int ks2 = kcol >> 4, cc2 = kcol & 15;
    int lane2 = (r2 & 7) * 4 + ((cc2 >> 1) & 3);
    int reg2 = (r2 >> 3) + 2 * (cc2 >> 3);
    int off = ya_off(strip2 * 4 + ks2, reg2, lane2);
    __nv_bfloat16 h0 = __float2bfloat16(d0);
    __nv_bfloat16 h1 = __float2bfloat16(d1);
    float h0f = __bfloat162float(h0), h1f = __bfloat162float(h1);
    *reinterpret_cast<uint32_t*>(smem + OFF_YAH + off) = pack2bf(h0f, h1f);
    *reinterpret_cast<uint32_t*>(smem + OFF_YAL + off) = pack2bf(d0 - h0f, d1 - h1f);
}

__global__ __launch_bounds__(THREADS, 1)
void ctrgc8(const float* __restrict__ x, float* __restrict__ out)
{
    const int tid = threadIdx.x;
    const int w = tid >> 5;      // warp 0..15
    const int lane = tid & 31;
    const int g = lane >> 2;
    const int tig = lane & 3;

    // ---- one-time init ----
    {
        uint4* wh = reinterpret_cast<uint4*>(smem + OFF_WAH);
        uint4* wl = reinterpret_cast<uint4*>(smem + OFF_WAL);
        for (int i = tid; i < 12 * 4 * 32; i += THREADS) { wh[i] = d_WfH[i]; wl[i] = d_WfL[i]; }
        unsigned long long* mh = reinterpret_cast<unsigned long long*>(smem + OFF_MBH);
        unsigned long long* ml = reinterpret_cast<unsigned long long*>(smem + OFF_MBL);
        for (int i = tid; i < 3 * 4 * 32; i += THREADS) { mh[i] = d_MfH[i]; ml[i] = d_MfL[i]; }
        uint32_t* ya = reinterpret_cast<uint32_t*>(smem + OFF_YAH);
        for (int i = tid; i < (2 * 28 * 4 * 4 * 32); i += THREADS) ya[i] = 0u;
    }
    __syncthreads();
    // bias column kcol=54: Y[row2][54] = Cf[o]  (pair (54,55), 55 stays 0)
    if (tid < 448) {
        float cf = d_Cf[tid & 63];
        ya_write(tid, 54, cf, 0.0f);
    }
    __syncthreads();

    const int tile0 = blockIdx.x * TILES_PER_CTA;

    // conversion lane constants
    const int cv_pos = w * 8 + g;
    const int cv_cbase = 2 * tig;

    // ---- prologue: convert tile0 into X B-frags (SoA) ----
    {
        int n = tile0 / TILES_PER_N;
        int j = tile0 - n * TILES_PER_N;
        int t0 = j * TT;
        int nvalid = ((t0 + TT <= TFULL) ? TT : (TFULL - t0)) * VD;
        const float* xb = x + (size_t)n * (CIN * TFULL * VD) + (size_t)t0 * VD;
#pragma unroll
        for (int u = 0; u < 8; u++) {
            int ks = u >> 1, reg = u & 1;
            int c0 = ks * 16 + reg * 8 + cv_cbase;
            float v0 = 0.0f, v1 = 0.0f;
            if (cv_pos < nvalid) {
                v0 = xb[c0 * (TFULL * VD) + cv_pos];
                v1 = xb[(c0 + 1) * (TFULL * VD) + cv_pos];
            }
            __nv_bfloat16 h0 = __float2bfloat16(v0), h1 = __float2bfloat16(v1);
            float h0f = __bfloat162float(h0), h1f = __bfloat162float(h1);
            int off = xb_off(w * 4 + ks, reg, lane);
            *reinterpret_cast<uint32_t*>(smem + OFF_XBH + off) = pack2bf(h0f, h1f);
            *reinterpret_cast<uint32_t*>(smem + OFF_XBL + off) = pack2bf(v0 - h0f, v1 - h1f);
        }
    }
    __syncthreads();

    for (int rel = 0; rel < TILES_PER_CTA; rel++) {
        const int tile = tile0 + rel;
        const int n  = tile / TILES_PER_N;
        const int j  = tile - n * TILES_PER_N;
        const int t0 = j * TT;
        const int valid_t = (t0 + TT <= TFULL) ? TT : (TFULL - t0);

        // ============ phase 1: stage A GEMM (4x4 blocking) + repack ==========
        {
            const int sg = w >> 2;   // strips {sg, sg+4, sg+8}
            const int pg = w & 3;    // posblks {pg, pg+4, pg+8, pg+12}

            // hoist X B-frags for this warp's 4 posblks (SoA reads, 64 regs)
            uint2 xbh[4][4], xbl[4][4];
#pragma unroll
            for (int p_i = 0; p_i < 4; p_i++) {
                int pb = pg + 4 * p_i;
#pragma unroll
                for (int ks = 0; ks < 4; ks++) {
                    int f = pb * 4 + ks;
                    xbh[p_i][ks].x = *reinterpret_cast<const uint32_t*>(smem + OFF_XBH + xb_off(f, 0, lane));
                    xbh[p_i][ks].y = *reinterpret_cast<const uint32_t*>(smem + OFF_XBH + xb_off(f, 1, lane));
                    xbl[p_i][ks].x = *reinterpret_cast<const uint32_t*>(smem + OFF_XBL + xb_off(f, 0, lane));
                    xbl[p_i][ks].y = *reinterpret_cast<const uint32_t*>(smem + OFF_XBL + xb_off(f, 1, lane));
                }
            }
#pragma unroll
            for (int s_i = 0; s_i < 3; s_i++) {
                const int s = sg + 4 * s_i;
                uint4 ah[4], al[4];
#pragma unroll
                for (int ks = 0; ks < 4; ks++) {
                    ah[ks] = *reinterpret_cast<const uint4*>(
                        smem + OFF_WAH + (((s * 4 + ks) * 32 + lane) << 4));
                    al[ks] = *reinterpret_cast<const uint4*>(
                        smem + OFF_WAL + (((s * 4 + ks) * 32 + lane) << 4));
                }
                const int rowA0 = s * 16 + g;
                const int k0 = rowA0 >> 6, o0 = rowA0 & 63;
                const int rowA1 = rowA0 + 8;
                const int k1 = rowA1 >> 6, o1 = rowA1 & 63;
#pragma unroll
                for (int p_i = 0; p_i < 4; p_i++) {
                    const int pb = pg + 4 * p_i;
                    const int p0 = pb * 8 + 2 * tig;
                    float D[4] = {0.0f, 0.0f, 0.0f, 0.0f};
#pragma unroll
                    for (int ks = 0; ks < 4; ks++) {
                        mma_bf16(D, ah[ks].x, ah[ks].y, ah[ks].z, ah[ks].w,
                                 xbh[p_i][ks].x, xbh[p_i][ks].y);
                        mma_bf16(D, ah[ks].x, ah[ks].y, ah[ks].z, ah[ks].w,
                                 xbl[p_i][ks].x, xbl[p_i][ks].y);
                        mma_bf16(D, al[ks].x, al[ks].y, al[ks].z, al[ks].w,
                                 xbh[p_i][ks].x, xbh[p_i][ks].y);
                    }
                    if (p0 < 126) {
                        int tloc = (p0 * 228) >> 12;
                        int vloc = p0 - 18 * tloc;
                        ya_write(tloc * 64 + o0, k0 * 18 + vloc, D[0], D[1]);
                        ya_write(tloc * 64 + o1, k1 * 18 + vloc, D[2], D[3]);
                    }
                }
            }
        }
        __syncthreads();

        // ====== phase 2: LDG(next) | stage B GEMM + relu/store | STS(next) ==
        const bool hasNext = (rel + 1 < TILES_PER_CTA);
        float pf[16];
        int nxt_nvalid = 0;
        if (hasNext) {
            int tn = tile + 1;
            int nn = tn / TILES_PER_N;
            int jn = tn - nn * TILES_PER_N;
            int tn0 = jn * TT;
            nxt_nvalid = ((tn0 + TT <= TFULL) ? TT : (TFULL - tn0)) * VD;
            const float* xb = x + (size_t)nn * (CIN * TFULL * VD) + (size_t)tn0 * VD;
#pragma unroll
            for (int u = 0; u < 8; u++) {
                int ks = u >> 1, reg = u & 1;
                int c0 = ks * 16 + reg * 8 + cv_cbase;
                bool okp = (cv_pos < nxt_nvalid);
                pf[2 * u]     = okp ? __ldg(xb + c0 * (TFULL * VD) + cv_pos) : 0.0f;
                pf[2 * u + 1] = okp ? __ldg(xb + (c0 + 1) * (TFULL * VD) + cv_pos) : 0.0f;
            }
        }

        // ---- stage B: M' frags hoisted (48 regs), strips {w, w+16} ----
        {
            uint2 mbh[3][4], mbl[3][4];
#pragma unroll
            for (int nb = 0; nb < 3; nb++)
#pragma unroll
                for (int ks = 0; ks < 4; ks++) {
                    mbh[nb][ks] = *reinterpret_cast<const uint2*>(
                        smem + OFF_MBH + (((nb * 4 + ks) * 32 + lane) << 3));
                    mbl[nb][ks] = *reinterpret_cast<const uint2*>(
                        smem + OFF_MBL + (((nb * 4 + ks) * 32 + lane) << 3));
                }
            for (int si = w; si < 28; si += 16) {
                uint4 ah[4], al[4];
#pragma unroll
                for (int ks = 0; ks < 4; ks++) {
                    int f = si * 4 + ks;
                    ah[ks].x = *reinterpret_cast<const uint32_t*>(smem + OFF_YAH + ya_off(f, 0, lane));
                    ah[ks].y = *reinterpret_cast<const uint32_t*>(smem + OFF_YAH + ya_off(f, 1, lane));
                    ah[ks].z = *reinterpret_cast<const uint32_t*>(smem + OFF_YAH + ya_off(f, 2, lane));
                    ah[ks].w = *reinterpret_cast<const uint32_t*>(smem + OFF_YAH + ya_off(f, 3, lane));
                    al[ks].x = *reinterpret_cast<const uint32_t*>(smem + OFF_YAL + ya_off(f, 0, lane));
                    al[ks].y = *reinterpret_cast<const uint32_t*>(smem + OFF_YAL + ya_off(f, 1, lane));
                    al[ks].z = *reinterpret_cast<const uint32_t*>(smem + OFF_YAL + ya_off(f, 2, lane));
                    al[ks].w = *reinterpret_cast<const uint32_t*>(smem + OFF_YAL + ya_off(f, 3, lane));
                }
                const int rowB = si * 16 + g;
                const int tB = rowB >> 6;
                const int oB = rowB & 63;
#pragma unroll
                for (int nb = 0; nb < 3; nb++) {
                    float D2[4] = {0.0f, 0.0f, 0.0f, 0.0f};
#pragma unroll
                    for (int ks = 0; ks < 4; ks++) {
                        mma_bf16(D2, ah[ks].x, ah[ks].y, ah[ks].z, ah[ks].w,
                                 mbh[nb][ks].x, mbh[nb][ks].y);
                        mma_bf16(D2, ah[ks].x, ah[ks].y, ah[ks].z, ah[ks].w,
                                 mbl[nb][ks].x, mbl[nb][ks].y);
                        mma_bf16(D2, al[ks].x, al[ks].y, al[ks].z, al[ks].w,
                                 mbh[nb][ks].x, mbh[nb][ks].y);
                    }
                    int w0 = nb * 8 + 2 * tig;
                    if (w0 < VD && tB < valid_t) {
                        size_t base = ((size_t)(n * 64 + oB) * TFULL + (t0 + tB)) * VD + w0;
                        *reinterpret_cast<float2*>(out + base) =
                            make_float2(fmaxf(D2[0], 0.0f), fmaxf(D2[1], 0.0f));
                        size_t base2 = base + (size_t)8 * TFULL * VD;   // o+8
                        *reinterpret_cast<float2*>(out + base2) =
                            make_float2(fmaxf(D2[2], 0.0f), fmaxf(D2[3], 0.0f));
                    }
                }
            }
        }

        // ---- convert next tile into X B-frags (SoA) ----
        if (hasNext) {
#pragma unroll
            for (int u = 0; u < 8; u++) {
                int ks = u >> 1, reg = u & 1;
                float v0 = pf[2 * u], v1 = pf[2 * u + 1];
                __nv_bfloat16 h0 = __float2bfloat16(v0), h1 = __float2bfloat16(v1);
                float h0f = __bfloat162float(h0), h1f = __bfloat162float(h1);
                int off = xb_off(w * 4 + ks, reg, lane);
                *reinterpret_cast<uint32_t*>(smem + OFF_XBH + off) = pack2bf(h0f, h1f);
                *reinterpret_cast<uint32_t*>(smem + OFF_XBL + off) = pack2bf(v0 - h0f, v1 - h1f);
            }
        }
        __syncthreads();
    }
}

extern "C" void kernel_launch(void* const* d_in, const int* in_sizes, int n_in,
                              void* d_out, int out_size)
{
    (void)in_sizes; (void)n_in; (void)out_size;
    const float* x    = (const float*)d_in[0];
    const float* A    = (const float*)d_in[1];
    const float* PA   = (const float*)d_in[2];
    const float* Wta  = (const float*)d_in[3];
    const float* bta  = (const float*)d_in[4];
    const float* g_ta = (const float*)d_in[5];
    const float* b_ta = (const float*)d_in[6];
    const float* m_ta = (const float*)d_in[7];
    const float* v_ta = (const float*)d_in[8];
    // d_in[9..12] dead attention branch
    const float* g_bn = (const float*)d_in[13];
    const float* b_bn = (const float*)d_in[14];
    const float* m_bn = (const float*)d_in[15];
    const float* v_bn = (const float*)d_in[16];
    float* out = (float*)d_out;

    cudaFuncSetAttribute(ctrgc8, cudaFuncAttributeMaxDynamicSharedMemorySize, SMEM_BYTES);

    prep_kernel<<<1, 256>>>(A, PA, Wta, bta, g_ta, b_ta, m_ta, v_ta,
                            g_bn, b_bn, m_bn, v_bn);
    ctrgc8<<<GRID, THREADS, SMEM_BYTES>>>(x, out);
}